// round 7
// baseline (speedup 1.0000x reference)
#include <cuda_runtime.h>
#include <math.h>

#define F_DIM 128
#define CAP   2048          // shared-memory logit/alpha cache per segment
#define N_MAX 2000000       // problem-fixed node count (scratch sizing)
#define G_MAX 16384

// Scratch (allocation-free rule: __device__ globals)
__device__ int   g_off[G_MAX + 1];
__device__ float g_logits[N_MAX];   // spill path only (len > CAP; ~never)

// ---------------------------------------------------------------------------
// Kernel 0: segment offsets via binary search on the sorted batch_idx array.
// g_off[g] = lower_bound(batch_idx, g); g_off[G] = N.
// ---------------------------------------------------------------------------
__global__ void offsets_kernel(const int* __restrict__ bidx, int N, int G) {
    int g = blockIdx.x * blockDim.x + threadIdx.x;
    if (g > G) return;
    int lo = 0, hi = N;
    while (lo < hi) {
        int mid = (lo + hi) >> 1;
        if (bidx[mid] < g) lo = mid + 1; else hi = mid;
    }
    g_off[g] = lo;
}

// ---------------------------------------------------------------------------
// Kernel 1: one CTA per graph/segment. 256 threads.
//   Pass 1: warp-per-row dot(x_row, w) + b  -> logits in shared
//   Reduce: segment max, then exp & segment sum (alphas cached in shared)
//   Pass 2: pooled[g][f] = sum_i alpha_i * x[i][f]
// ---------------------------------------------------------------------------
__global__ __launch_bounds__(256) void pool_kernel(
    const float* __restrict__ x,
    const float* __restrict__ w,
    const float* __restrict__ bptr,
    float* __restrict__ out)
{
    __shared__ float s_alpha[CAP];   // holds logits, then exp(logit - max)
    __shared__ float s_red[256];

    const int g     = blockIdx.x;
    const int start = g_off[g];
    const int len   = g_off[g + 1] - start;
    const int tid   = threadIdx.x;

    if (len == 0) {
        // empty segment: reference yields zeros (seg_max guarded, empty sum = 0)
        if (tid < F_DIM) out[(size_t)g * F_DIM + tid] = 0.0f;
        return;
    }

    const float b    = *bptr;
    const int   wid  = tid >> 5;
    const int   lane = tid & 31;

    // each lane holds its 4 weight components for the whole block
    const float4 wv = reinterpret_cast<const float4*>(w)[lane];

    // -------- Pass 1: logits (warp per row, float4 per lane = 512B/row) ----
    const bool spill = (len > CAP);
    for (int i = wid; i < len; i += 8) {
        const float4* xr = reinterpret_cast<const float4*>(x + (size_t)(start + i) * F_DIM);
        float4 xv = xr[lane];
        float d = xv.x * wv.x + xv.y * wv.y + xv.z * wv.z + xv.w * wv.w;
        #pragma unroll
        for (int o = 16; o > 0; o >>= 1)
            d += __shfl_down_sync(0xffffffffu, d, o);
        if (lane == 0) {
            float l = d + b;
            if (i < CAP) s_alpha[i] = l;
            if (spill)   g_logits[start + i] = l;
        }
    }
    __syncthreads();

    // -------- Segment max ---------------------------------------------------
    float m = -INFINITY;
    for (int i = tid; i < len; i += 256)
        m = fmaxf(m, (i < CAP) ? s_alpha[i] : g_logits[start + i]);
    s_red[tid] = m;
    __syncthreads();
    #pragma unroll
    for (int s = 128; s > 0; s >>= 1) {
        if (tid < s) s_red[tid] = fmaxf(s_red[tid], s_red[tid + s]);
        __syncthreads();
    }
    m = s_red[0];
    __syncthreads();

    // -------- exp + segment sum (cache exp values in shared) ---------------
    float psum = 0.0f;
    for (int i = tid; i < len; i += 256) {
        float l = (i < CAP) ? s_alpha[i] : g_logits[start + i];
        float e = expf(l - m);
        psum += e;
        if (i < CAP) s_alpha[i] = e;
    }
    s_red[tid] = psum;
    __syncthreads();
    #pragma unroll
    for (int s = 128; s > 0; s >>= 1) {
        if (tid < s) s_red[tid] += s_red[tid + s];
        __syncthreads();
    }
    const float inv = 1.0f / (s_red[0] + 1e-16f);
    __syncthreads();   // protect s_red / s_alpha before pass 2 reuse

    // -------- Pass 2: weighted pool. thread f = tid&127, two row-halves ----
    const int f = tid & 127;
    const int h = tid >> 7;
    float acc = 0.0f;
    for (int i = h; i < len; i += 2) {
        float a = (i < CAP) ? s_alpha[i] : expf(g_logits[start + i] - m);
        acc = fmaf(a, x[(size_t)(start + i) * F_DIM + f], acc);
    }
    acc *= inv;
    s_red[tid] = acc;
    __syncthreads();
    if (tid < 128)
        out[(size_t)g * F_DIM + tid] = s_red[tid] + s_red[tid + 128];
}

// ---------------------------------------------------------------------------
// Launch contract
// Inputs (metadata order): x [N*128] f32, attn_w [128] f32, attn_b [1] f32,
//                          batch_idx [N] i32, (num_graphs scalar, unused)
// Output: pooled [G*128] f32
// ---------------------------------------------------------------------------
extern "C" void kernel_launch(void* const* d_in, const int* in_sizes, int n_in,
                              void* d_out, int out_size) {
    const float* x    = (const float*)d_in[0];
    const float* w    = (const float*)d_in[1];
    const float* bptr = (const float*)d_in[2];
    const int*   bidx = (const int*)d_in[3];

    const int N = in_sizes[3];              // node count from batch_idx length
    const int G = out_size / F_DIM;         // 16384

    offsets_kernel<<<(G + 1 + 255) / 256, 256>>>(bidx, N, G);
    pool_kernel<<<G, 256>>>(x, w, bptr, (float*)d_out);
}

// round 9
// speedup vs baseline: 1.6195x; 1.6195x over previous
#include <cuda_runtime.h>
#include <math.h>

#define F_DIM 128
#define G_MAX 16384

// Allocation-free scratch
__device__ int g_off[G_MAX + 1];

// ---------------------------------------------------------------------------
// Kernel 0: segment offsets via binary search on sorted batch_idx.
// ---------------------------------------------------------------------------
__global__ void offsets_kernel(const int* __restrict__ bidx, int N, int G) {
    int g = blockIdx.x * blockDim.x + threadIdx.x;
    if (g > G) return;
    int lo = 0, hi = N;
    while (lo < hi) {
        int mid = (lo + hi) >> 1;
        if (bidx[mid] < g) lo = mid + 1; else hi = mid;
    }
    g_off[g] = lo;
}

// ---------------------------------------------------------------------------
// Kernel 1: one CTA (256 thr) per segment. Single pass over x with per-warp
// online softmax; rows live in registers between logit and accumulate.
//   warp w owns rows {w, w+8, ...}; lane holds float4 of features 4*lane..+3.
//   per-warp state: running max m, running sum s, running weighted acc4.
//   merge 8 warps at the end via shared (m_w, s_w, acc_w[128]).
// ---------------------------------------------------------------------------
__global__ __launch_bounds__(256) void pool_kernel(
    const float* __restrict__ x,
    const float* __restrict__ w,
    const float* __restrict__ bptr,
    float* __restrict__ out)
{
    __shared__ float s_m[8];
    __shared__ float s_s[8];
    __shared__ float s_acc[8][F_DIM];

    const int g     = blockIdx.x;
    const int start = g_off[g];
    const int len   = g_off[g + 1] - start;
    const int tid   = threadIdx.x;

    if (len == 0) {   // empty segment -> zeros (matches reference guard)
        if (tid < F_DIM) out[(size_t)g * F_DIM + tid] = 0.0f;
        return;
    }

    const int wid  = tid >> 5;
    const int lane = tid & 31;
    const float b  = __ldg(bptr);
    const float4 wv = reinterpret_cast<const float4*>(w)[lane];

    float  m = -INFINITY;
    float  s = 0.0f;
    float4 acc = make_float4(0.f, 0.f, 0.f, 0.f);

    // row pointer for this warp/lane; stride 8 rows = 256 float4
    const float4* xp = reinterpret_cast<const float4*>(x)
                     + (size_t)(start + wid) * 32 + lane;

    int i = wid;
    float4 nxt = (i < len) ? *xp : make_float4(0.f, 0.f, 0.f, 0.f);
    while (i < len) {
        float4 cur = nxt;
        i  += 8;
        xp += 256;
        if (i < len) nxt = *xp;              // software prefetch (MLP)

        float d = cur.x * wv.x + cur.y * wv.y + cur.z * wv.z + cur.w * wv.w;
        #pragma unroll
        for (int o = 16; o > 0; o >>= 1)
            d += __shfl_xor_sync(0xffffffffu, d, o);   // all lanes get full dot
        const float l = d + b;               // logit (uniform across warp)

        if (l > m) {                          // new max: rescale history
            float c = __expf(m - l);          // exp(-inf)=0 on first row
            s = fmaf(s, c, 1.0f);
            acc.x = fmaf(acc.x, c, cur.x);
            acc.y = fmaf(acc.y, c, cur.y);
            acc.z = fmaf(acc.z, c, cur.z);
            acc.w = fmaf(acc.w, c, cur.w);
            m = l;
        } else {
            float e = __expf(l - m);
            s += e;
            acc.x = fmaf(e, cur.x, acc.x);
            acc.y = fmaf(e, cur.y, acc.y);
            acc.z = fmaf(e, cur.z, acc.z);
            acc.w = fmaf(e, cur.w, acc.w);
        }
    }

    if (lane == 0) { s_m[wid] = m; s_s[wid] = s; }
    reinterpret_cast<float4*>(s_acc[wid])[lane] = acc;
    __syncthreads();

    // -------- merge the 8 per-warp online-softmax states --------------------
    if (tid < F_DIM) {
        float M = s_m[0];
        #pragma unroll
        for (int k = 1; k < 8; k++) M = fmaxf(M, s_m[k]);
        float S = 0.0f, a = 0.0f;
        #pragma unroll
        for (int k = 0; k < 8; k++) {
            float c = __expf(s_m[k] - M);     // empty warp: exp(-inf)=0
            S = fmaf(s_s[k], c, S);
            a = fmaf(s_acc[k][tid], c, a);
        }
        out[(size_t)g * F_DIM + tid] = a / (S + 1e-16f);
    }
}

// ---------------------------------------------------------------------------
// Inputs: x [N*128] f32, attn_w [128] f32, attn_b [1] f32, batch_idx [N] i32
// Output: pooled [G*128] f32
// ---------------------------------------------------------------------------
extern "C" void kernel_launch(void* const* d_in, const int* in_sizes, int n_in,
                              void* d_out, int out_size) {
    const float* x    = (const float*)d_in[0];
    const float* w    = (const float*)d_in[1];
    const float* bptr = (const float*)d_in[2];
    const int*   bidx = (const int*)d_in[3];

    const int N = in_sizes[3];
    const int G = out_size / F_DIM;

    offsets_kernel<<<(G + 1 + 255) / 256, 256>>>(bidx, N, G);
    pool_kernel<<<G, 256>>>(x, w, bptr, (float*)d_out);
}